// round 16
// baseline (speedup 1.0000x reference)
#include <cuda_runtime.h>
#include <cuda_bf16.h>
#include <math.h>
#include <stdint.h>

// ---------------------------------------------------------------------------
// Problem constants
// ---------------------------------------------------------------------------
#define CC 128
#define NTOK 98
#define BWIN 2048
#define LTOK 25088
#define MROWS 200704
#define HID 512
#define SCALE 0.17677669529663687f
#define EPS 1e-5f

// ---------------------------------------------------------------------------
// Scratch
// ---------------------------------------------------------------------------
__device__ __nv_bfloat16 g_bh1[(size_t)MROWS * 384];  // qkv out
__device__ __nv_bfloat16 g_bh2[(size_t)MROWS * CC];   // attn out (window layout)
__device__ float g_bufB[(size_t)MROWS * CC];          // x2 residual (token layout)
__device__ __nv_bfloat16 g_biasMask[32 * 112 * 112];  // combined bias+mask, bf16
__device__ __nv_bfloat16 g_wt[196608];                // transposed bf16 weights [N][K]

#define WT_QKV 0        // 384 x 128
#define WT_PROJ 49152   // 128 x 128
#define WT_FC1 65536    // 512 x 128
#define WT_FC2 131072   // 128 x 512

// ---------------------------------------------------------------------------
// HMMA + ldmatrix helpers (baseline PTX, sm_75/80+)
// ---------------------------------------------------------------------------
__device__ __forceinline__ void mma16816(float* c, const uint32_t* a, const uint32_t* b) {
    asm volatile(
        "mma.sync.aligned.m16n8k16.row.col.f32.bf16.bf16.f32 "
        "{%0,%1,%2,%3}, {%4,%5,%6,%7}, {%8,%9}, {%0,%1,%2,%3};"
        : "+f"(c[0]), "+f"(c[1]), "+f"(c[2]), "+f"(c[3])
        : "r"(a[0]), "r"(a[1]), "r"(a[2]), "r"(a[3]), "r"(b[0]), "r"(b[1]));
}
__device__ __forceinline__ uint32_t su32(const void* p) {
    return (uint32_t)__cvta_generic_to_shared(p);
}
__device__ __forceinline__ void ldm4(uint32_t* r, uint32_t addr) {
    asm volatile("ldmatrix.sync.aligned.m8n8.x4.shared.b16 {%0,%1,%2,%3}, [%4];"
                 : "=r"(r[0]), "=r"(r[1]), "=r"(r[2]), "=r"(r[3]) : "r"(addr));
}

// cp.async 16B
__device__ __forceinline__ void cp16(void* sdst, const void* gsrc) {
    uint32_t sa = (uint32_t)__cvta_generic_to_shared(sdst);
    asm volatile("cp.async.cg.shared.global [%0], [%1], 16;" :: "r"(sa), "l"(gsrc));
}
__device__ __forceinline__ void cp_commit() {
    asm volatile("cp.async.commit_group;");
}
template <int N>
__device__ __forceinline__ void cp_wait() {
    asm volatile("cp.async.wait_group %0;" :: "n"(N));
}

__device__ __forceinline__ uint32_t packbf2(float a, float b) {
    __nv_bfloat162 t = __floats2bfloat162_rn(a, b);
    return *(uint32_t*)&t;
}
__device__ __forceinline__ float gelu1(float v) {
    return 0.5f * v * (1.0f + erff(v * 0.7071067811865475f));
}

// ---------------------------------------------------------------------------
// Combined prep: weight transposes + combined bias/mask table.
// Table layout: [cls*4+head][i][j], cls = (tw==3)*4 + (hw==7)*2 + (ww==7)
// ---------------------------------------------------------------------------
#define PREP_QKV_END  49152
#define PREP_PROJ_END 65536
#define PREP_FC1_END  131072
#define PREP_FC2_END  196608
#define PREP_TOTAL    (196608 + 32 * 112 * 112)

__device__ __forceinline__ int regid(int tok, int tb, int hb, int wb) {
    int t0 = tok / 49, r = tok % 49, h0 = r / 7, w0 = r % 7;
    int rt = tb ? (t0 == 0 ? 1 : 2) : 0;
    int rh = hb ? (h0 < 4 ? 1 : 2) : 0;
    int rw = wb ? (w0 < 4 ? 1 : 2) : 0;
    return rt * 9 + rh * 3 + rw;
}

__global__ void prep_kernel(const float* __restrict__ qkv_w,
                            const float* __restrict__ proj_w,
                            const float* __restrict__ fc1_w,
                            const float* __restrict__ fc2_w,
                            const float* __restrict__ rpb) {
    int idx = blockIdx.x * blockDim.x + threadIdx.x;
    if (idx >= PREP_TOTAL) return;
    if (idx < PREP_QKV_END) {
        int l = idx; int k = l / 384, n = l % 384;
        g_wt[WT_QKV + n * 128 + k] = __float2bfloat16(qkv_w[l]);
    } else if (idx < PREP_PROJ_END) {
        int l = idx - PREP_QKV_END; int k = l / 128, n = l % 128;
        g_wt[WT_PROJ + n * 128 + k] = __float2bfloat16(proj_w[l]);
    } else if (idx < PREP_FC1_END) {
        int l = idx - PREP_PROJ_END; int k = l / 512, n = l % 512;
        g_wt[WT_FC1 + n * 128 + k] = __float2bfloat16(fc1_w[l]);
    } else if (idx < PREP_FC2_END) {
        int l = idx - PREP_FC1_END; int k = l / 128, n = l % 128;
        g_wt[WT_FC2 + n * 512 + k] = __float2bfloat16(fc2_w[l]);
    } else {
        int m = idx - PREP_FC2_END;
        int cls = m / 50176;
        int rem = m % 50176;
        int h = rem / 12544;
        int rr = rem % 12544;
        int i = rr / 112, j = rr % 112;
        float v = 0.f;
        if (i < NTOK && j < NTOK) {
            int ti = i / 49, hi = (i / 7) % 7, wi = i % 7;
            int tj = j / 49, hj = (j / 7) % 7, wj = j % 7;
            int ridx = (ti - tj + 1) * 169 + (hi - hj + 6) * 13 + (wi - wj + 6);
            v = rpb[ridx * 4 + h];
            int tb = (cls >> 2) & 1, hb = (cls >> 1) & 1, wb = cls & 1;
            if (regid(i, tb, hb, wb) != regid(j, tb, hb, wb)) v += -100.f;
        }
        g_biasMask[m] = __float2bfloat16(v);
    }
}

// window-layout row -> token row (shift/roll gather mapping)
__device__ __forceinline__ int win2tok(int row) {
    int bwin = row / NTOK, n = row % NTOK;
    int b = bwin >> 8, win = bwin & 255;
    int tw = win >> 6, hw = (win >> 3) & 7, ww = win & 7;
    int t0 = n / 49, r49 = n % 49, h0 = r49 / 7, w0 = r49 % 7;
    int tg = (tw * 2 + t0 + 1) & 7;
    int hg = hw * 7 + h0 + 3; if (hg >= 56) hg -= 56;
    int wg = ww * 7 + w0 + 3; if (wg >= 56) wg -= 56;
    return b * LTOK + (tg * 56 + hg) * 56 + wg;
}

// ---------------------------------------------------------------------------
// Fused LN1 + shift/window-gather + QKV GEMM (A resident, 3 n-tiles)
// ---------------------------------------------------------------------------
#define NSTR 136
#define NL_TILE_BYTES (128 * NSTR * 2)
#define NL_SMEM (3 * NL_TILE_BYTES)

__global__ __launch_bounds__(256) void lnqkv_kernel(
        const float* __restrict__ x, const float* __restrict__ lng,
        const float* __restrict__ lnb, const __nv_bfloat16* __restrict__ Wt,
        const float* __restrict__ bias, __nv_bfloat16* __restrict__ out) {
    extern __shared__ __align__(16) char smem[];
    __nv_bfloat16* sA = (__nv_bfloat16*)smem;

    int t = threadIdx.x;
    int warp = t >> 5, lane = t & 31;
    int wm = warp & 1, wn = warp >> 1;
    int gid = lane >> 2, tig = lane & 3;
    int lr8 = lane & 7, lm = lane >> 3;
    int m0 = blockIdx.x << 7;
    const int NT = 3, Np = 384;

    {
        __nv_bfloat16* sB0 = (__nv_bfloat16*)(smem + NL_TILE_BYTES);
#pragma unroll
        for (int it = 0; it < 8; it++) {
            int c = t + (it << 8);
            int r = c >> 4, c8 = (c & 15) << 3;
            cp16(&sB0[r * NSTR + c8], Wt + (size_t)r * 128 + c8);
        }
        cp_commit();
    }

    // LN1 + gather into sA
    {
        float4 gv = *(const float4*)(lng + lane * 4);
        float4 bv = *(const float4*)(lnb + lane * 4);
#pragma unroll
        for (int i = 0; i < 16; i++) {
            int row = warp * 16 + i;
            int tok = win2tok(m0 + row);
            float4 v = *(const float4*)(x + (size_t)tok * CC + lane * 4);
            float s = v.x + v.y + v.z + v.w;
#pragma unroll
            for (int o = 16; o > 0; o >>= 1) s += __shfl_xor_sync(0xffffffffu, s, o);
            float mean = s * (1.0f / CC);
            float dx = v.x - mean, dy = v.y - mean, dz = v.z - mean, dw = v.w - mean;
            float q = dx * dx + dy * dy + dz * dz + dw * dw;
#pragma unroll
            for (int o = 16; o > 0; o >>= 1) q += __shfl_xor_sync(0xffffffffu, q, o);
            float rstd = rsqrtf(q * (1.0f / CC) + EPS);
            uint32_t p0 = packbf2(dx * rstd * gv.x + bv.x, dy * rstd * gv.y + bv.y);
            uint32_t p1 = packbf2(dz * rstd * gv.z + bv.z, dw * rstd * gv.w + bv.w);
            *(uint2*)&sA[row * NSTR + lane * 4] = make_uint2(p0, p1);
        }
    }

    uint32_t aBase = su32(sA) + (uint32_t)((wm * 64 + lr8 + (lm & 1) * 8) * NSTR
                                           + (lm >> 1) * 8) * 2;

    for (int nt = 0; nt < NT; nt++) {
        if (nt + 1 < NT) {
            __nv_bfloat16* sBn = (__nv_bfloat16*)(smem + NL_TILE_BYTES
                                                  + ((nt + 1) & 1) * NL_TILE_BYTES);
            const __nv_bfloat16* Bg = Wt + (size_t)(nt + 1) * 128 * 128;
#pragma unroll
            for (int it = 0; it < 8; it++) {
                int c = t + (it << 8);
                int r = c >> 4, c8 = (c & 15) << 3;
                cp16(&sBn[r * NSTR + c8], Bg + (size_t)r * 128 + c8);
            }
            cp_commit();
            cp_wait<1>();
        } else {
            cp_wait<0>();
        }
        __syncthreads();
        const __nv_bfloat16* sB = (const __nv_bfloat16*)(smem + NL_TILE_BYTES
                                                         + (nt & 1) * NL_TILE_BYTES);
        uint32_t bBase = su32(sB) + (uint32_t)((wn * 32 + lr8 + (lm >> 1) * 8) * NSTR
                                               + (lm & 1) * 8) * 2;
        float acc[4][4][4];
#pragma unroll
        for (int mt = 0; mt < 4; mt++)
#pragma unroll
            for (int ntx = 0; ntx < 4; ntx++)
#pragma unroll
                for (int e = 0; e < 4; e++) acc[mt][ntx][e] = 0.f;

#pragma unroll
        for (int ks = 0; ks < 8; ks++) {
            int k0 = ks << 4;
            uint32_t af[4][4], bq[2][4];
#pragma unroll
            for (int mt = 0; mt < 4; mt++)
                ldm4(af[mt], aBase + (uint32_t)(mt * 16 * NSTR + k0) * 2);
#pragma unroll
            for (int n2 = 0; n2 < 2; n2++)
                ldm4(bq[n2], bBase + (uint32_t)(n2 * 16 * NSTR + k0) * 2);
#pragma unroll
            for (int mt = 0; mt < 4; mt++)
#pragma unroll
                for (int n2 = 0; n2 < 2; n2++) {
                    mma16816(acc[mt][2 * n2], af[mt], bq[n2]);
                    mma16816(acc[mt][2 * n2 + 1], af[mt], bq[n2] + 2);
                }
        }
        __syncthreads();

        int ncol0 = nt * 128;
#pragma unroll
        for (int mt = 0; mt < 4; mt++) {
            int row = m0 + wm * 64 + mt * 16 + gid;
#pragma unroll
            for (int ntx = 0; ntx < 4; ntx++) {
                int col = ncol0 + wn * 32 + ntx * 8 + tig * 2;
                float b0 = bias[col], b1 = bias[col + 1];
                *(__nv_bfloat162*)(out + (size_t)row * Np + col) =
                    __floats2bfloat162_rn(acc[mt][ntx][0] + b0, acc[mt][ntx][1] + b1);
                *(__nv_bfloat162*)(out + (size_t)(row + 8) * Np + col) =
                    __floats2bfloat162_rn(acc[mt][ntx][2] + b0, acc[mt][ntx][3] + b1);
            }
        }
    }
}

// ---------------------------------------------------------------------------
// Proj GEMM (BK=32 double-buffered, K=128) fused with scatter + residual.
// (LN2 moved into the FFN kernel.) Two-phase 64-row epilogue spill, 40KB smem.
// ---------------------------------------------------------------------------
#define SSTR 40
#define STAGE_BYTES (2 * 128 * SSTR * 2)
#define GEMM_SMEM   (2 * STAGE_BYTES)      // 40960

__global__ __launch_bounds__(256) void proj_fused_kernel(
        const __nv_bfloat16* __restrict__ A, const __nv_bfloat16* __restrict__ Wt,
        const float* __restrict__ bias,
        const float* __restrict__ xres, float* __restrict__ x2out) {
    extern __shared__ __align__(16) char smem[];
    const int K = 128;

    int t = threadIdx.x;
    int warp = t >> 5, lane = t & 31;
    int wm = warp & 1, wn = warp >> 1;
    int gid = lane >> 2, tig = lane & 3;
    int lr8 = lane & 7, lm = lane >> 3;
    int m0 = blockIdx.x << 7;

    float acc[4][4][4];
#pragma unroll
    for (int mt = 0; mt < 4; mt++)
#pragma unroll
        for (int nt = 0; nt < 4; nt++)
#pragma unroll
            for (int e = 0; e < 4; e++) acc[mt][nt][e] = 0.f;

    int lr = t >> 2;
    int lc = (t & 3) << 3;

    const __nv_bfloat16* Ag = A + (size_t)(m0 + lr) * K + lc;
    const __nv_bfloat16* Bg = Wt + (size_t)lr * K + lc;
    int sa0 = (lr * SSTR + lc) * 2;
    int sa1 = ((lr + 64) * SSTR + lc) * 2;

    uint32_t aOff = (uint32_t)((wm * 64 + lr8 + (lm & 1) * 8) * SSTR + (lm >> 1) * 8) * 2;
    uint32_t bOff = (uint32_t)((wn * 32 + lr8 + (lm >> 1) * 8) * SSTR + (lm & 1) * 8) * 2
                    + 128 * SSTR * 2;

    {
        char* st = smem;
        cp16(st + sa0, Ag);
        cp16(st + sa1, Ag + (size_t)64 * K);
        cp16(st + 10240 + sa0, Bg);
        cp16(st + 10240 + sa1, Bg + (size_t)64 * K);
        cp_commit();
    }

    for (int kc = 0; kc < 4; kc++) {
        if (kc + 1 < 4) {
            char* st = smem + ((kc + 1) & 1) * STAGE_BYTES;
            int kt = (kc + 1) << 5;
            cp16(st + sa0, Ag + kt);
            cp16(st + sa1, Ag + (size_t)64 * K + kt);
            cp16(st + 10240 + sa0, Bg + kt);
            cp16(st + 10240 + sa1, Bg + (size_t)64 * K + kt);
            cp_commit();
            cp_wait<1>();
        } else {
            cp_wait<0>();
        }
        __syncthreads();
        uint32_t stageu = su32(smem) + (uint32_t)((kc & 1) * STAGE_BYTES);
#pragma unroll
        for (int ks = 0; ks < 2; ks++) {
            int k0 = ks << 4;
            uint32_t af[4][4], bq[2][4];
#pragma unroll
            for (int mt = 0; mt < 4; mt++)
                ldm4(af[mt], stageu + aOff + (uint32_t)(mt * 16 * SSTR + k0) * 2);
#pragma unroll
            for (int n2 = 0; n2 < 2; n2++)
                ldm4(bq[n2], stageu + bOff + (uint32_t)(n2 * 16 * SSTR + k0) * 2);
#pragma unroll
            for (int mt = 0; mt < 4; mt++)
#pragma unroll
                for (int n2 = 0; n2 < 2; n2++) {
                    mma16816(acc[mt][2 * n2], af[mt], bq[n2]);
                    mma16816(acc[mt][2 * n2 + 1], af[mt], bq[n2] + 2);
                }
        }
        __syncthreads();
    }

    // two-phase epilogue: spill + scatter + residual per 64-row half
    float* sout = (float*)smem;   // 64 x 132 fp32
#pragma unroll
    for (int ph = 0; ph < 2; ph++) {
        if (wm == ph) {
#pragma unroll
            for (int mt = 0; mt < 4; mt++) {
                int row = mt * 16 + gid;
#pragma unroll
                for (int nt = 0; nt < 4; nt++) {
                    int col = wn * 32 + nt * 8 + tig * 2;
                    float b0 = bias[col], b1 = bias[col + 1];
                    sout[row * 132 + col] = acc[mt][nt][0] + b0;
                    sout[row * 132 + col + 1] = acc[mt][nt][1] + b1;
                    sout[(row + 8) * 132 + col] = acc[mt][nt][2] + b0;
                    sout[(row + 8) * 132 + col + 1] = acc[mt][nt][3] + b1;
                }
            }
        }
        __syncthreads();
#pragma unroll
        for (int i = 0; i < 8; i++) {
            int row = warp * 8 + i;
            int tr = win2tok(m0 + ph * 64 + row);
            const float* xr = xres + (size_t)tr * CC;
            float* dx2 = x2out + (size_t)tr * CC;
#pragma unroll
            for (int k = 0; k < 4; k++) {
                int c = lane + 32 * k;
                dx2[c] = sout[row * 132 + c] + xr[c];
            }
        }
        __syncthreads();
    }
}

// ---------------------------------------------------------------------------
// Fused LN2 + FFN, interleaved (64-row CTA, 2 CTAs/SM).
// LN2 computed from x2 into sA during the W1 tile-0 prefetch.
// ---------------------------------------------------------------------------
#define FF_SA_BYTES (64 * NSTR * 2)
#define FF_SH_BYTES (64 * NSTR * 2)
#define FF_SB_BYTES (128 * NSTR * 2)
#define FF_SMEM (FF_SA_BYTES + FF_SH_BYTES + 2 * FF_SB_BYTES)

__global__ __launch_bounds__(256) void ffn_kernel(
        const float* __restrict__ x2,             // residual stream [M,128] fp32
        const float* __restrict__ ln_g, const float* __restrict__ ln_b,
        const __nv_bfloat16* __restrict__ w1,
        const __nv_bfloat16* __restrict__ w2,
        const float* __restrict__ b1, const float* __restrict__ b2,
        float* __restrict__ out) {
    extern __shared__ __align__(16) char smem[];
    __nv_bfloat16* sA = (__nv_bfloat16*)smem;
    __nv_bfloat16* sH = (__nv_bfloat16*)(smem + FF_SA_BYTES);
    char* sBbase = smem + FF_SA_BYTES + FF_SH_BYTES;

    int t = threadIdx.x;
    int warp = t >> 5, lane = t & 31;
    int wm = warp & 1, wn = warp >> 1;
    int gid = lane >> 2, tig = lane & 3;
    int lr8 = lane & 7, lm = lane >> 3;
    int m0 = blockIdx.x << 6;

    // W1 tile 0 prefetch first (overlaps LN below)
    {
        __nv_bfloat16* sB0 = (__nv_bfloat16*)sBbase;
#pragma unroll
        for (int it = 0; it < 8; it++) {
            int c = t + (it << 8);
            int r = c >> 4, c8 = (c & 15) << 3;
            cp16(&sB0[r * NSTR + c8], w1 + (size_t)r * 128 + c8);
        }
        cp_commit();
    }

    // LN2 from x2 -> sA (bf16); warp handles rows warp*8 .. +7
    {
        float4 gv = *(const float4*)(ln_g + lane * 4);
        float4 bv = *(const float4*)(ln_b + lane * 4);
#pragma unroll
        for (int i = 0; i < 8; i++) {
            int row = warp * 8 + i;
            float4 v = *(const float4*)(x2 + (size_t)(m0 + row) * CC + lane * 4);
            float s = v.x + v.y + v.z + v.w;
#pragma unroll
            for (int o = 16; o > 0; o >>= 1) s += __shfl_xor_sync(0xffffffffu, s, o);
            float mean = s * (1.0f / CC);
            float dx = v.x - mean, dy = v.y - mean, dz = v.z - mean, dw = v.w - mean;
            float q = dx * dx + dy * dy + dz * dz + dw * dw;
#pragma unroll
            for (int o = 16; o > 0; o >>= 1) q += __shfl_xor_sync(0xffffffffu, q, o);
            float rstd = rsqrtf(q * (1.0f / CC) + EPS);
            uint32_t p0 = packbf2(dx * rstd * gv.x + bv.x, dy * rstd * gv.y + bv.y);
            uint32_t p1 = packbf2(dz * rstd * gv.z + bv.z, dw * rstd * gv.w + bv.w);
            *(uint2*)&sA[row * NSTR + lane * 4] = make_uint2(p0, p1);
        }
    }

    uint32_t aBase = su32(sA) + (uint32_t)((wm * 32 + lr8 + (lm & 1) * 8) * NSTR
                                           + (lm >> 1) * 8) * 2;
    uint32_t hWBase = su32(sH) + (uint32_t)((wm * 32 + lr8 + (lm & 1) * 8) * NSTR
                                            + (lm >> 1) * 8) * 2;

    float acc2[2][4][4];
#pragma unroll
    for (int mt = 0; mt < 2; mt++)
#pragma unroll
        for (int nt = 0; nt < 4; nt++)
#pragma unroll
            for (int e = 0; e < 4; e++) acc2[mt][nt][e] = 0.f;

    for (int j = 0; j < 8; j++) {
        if (j + 1 < 8) {
            __nv_bfloat16* sBn = (__nv_bfloat16*)(sBbase + ((j + 1) & 1) * FF_SB_BYTES);
            int jn = j + 1;
            if ((jn & 1) == 0) {
                const __nv_bfloat16* Bg = w1 + (size_t)(jn >> 1) * 128 * 128;
#pragma unroll
                for (int it = 0; it < 8; it++) {
                    int c = t + (it << 8);
                    int r = c >> 4, c8 = (c & 15) << 3;
                    cp16(&sBn[r * NSTR + c8], Bg + (size_t)r * 128 + c8);
                }
            } else {
                const __nv_bfloat16* Bg = w2 + (size_t)(jn >> 1) * 128;
#pragma unroll
                for (int it = 0; it < 8; it++) {
                    int c = t + (it << 8);
                    int r = c >> 4, c8 = (c & 15) << 3;
                    cp16(&sBn[r * NSTR + c8], Bg + (size_t)r * 512 + c8);
                }
            }
            cp_commit();
            cp_wait<1>();
        } else {
            cp_wait<0>();
        }
        __syncthreads();
        const __nv_bfloat16* sB = (const __nv_bfloat16*)(sBbase + (j & 1) * FF_SB_BYTES);
        uint32_t bBase = su32(sB) + (uint32_t)((wn * 32 + lr8 + (lm >> 1) * 8) * NSTR
                                               + (lm & 1) * 8) * 2;

        if ((j & 1) == 0) {
            float acc[2][4][4];
#pragma unroll
            for (int mt = 0; mt < 2; mt++)
#pragma unroll
                for (int nt = 0; nt < 4; nt++)
#pragma unroll
                    for (int e = 0; e < 4; e++) acc[mt][nt][e] = 0.f;
#pragma unroll
            for (int ks = 0; ks < 8; ks++) {
                int k0 = ks << 4;
                uint32_t af[2][4], bq[2][4];
#pragma unroll
                for (int mt = 0; mt < 2; mt++)
                    ldm4(af[mt], aBase + (uint32_t)(mt * 16 * NSTR + k0) * 2);
#pragma unroll
                for (int n2 = 0; n2 < 2; n2++)
                    ldm4(bq[n2], bBase + (uint32_t)(n2 * 16 * NSTR + k0) * 2);
#pragma unroll
                for (int mt = 0; mt < 2; mt++)
#pragma unroll
                    for (int n2 = 0; n2 < 2; n2++) {
                        mma16816(acc[mt][2 * n2], af[mt], bq[n2]);
                        mma16816(acc[mt][2 * n2 + 1], af[mt], bq[n2] + 2);
                    }
            }
            int hc0 = (j >> 1) * 128;
#pragma unroll
            for (int mt = 0; mt < 2; mt++) {
                int row = wm * 32 + mt * 16 + gid;
#pragma unroll
                for (int nt = 0; nt < 4; nt++) {
                    int col = wn * 32 + nt * 8 + tig * 2;
                    float bb0 = b1[hc0 + col], bb1 = b1[hc0 + col + 1];
                    *(uint32_t*)&sH[row * NSTR + col] =
                        packbf2(gelu1(acc[mt][nt][0] + bb0), gelu1(acc[mt][nt][1] + bb1));
                    *(uint32_t*)&sH[(row + 8) * NSTR + col] =
                        packbf2(gelu1(acc[mt][nt][2] + bb0), gelu1(acc[mt][nt][3] + bb1));
                }
            }
        } else {
            __syncthreads();
#pragma unroll
            for (int ks = 0; ks < 8; ks++) {
                int k0 = ks << 4;
                uint32_t af[2][4], bq[2][4];
#pragma unroll
                for (int mt = 0; mt < 2; mt++)
                    ldm4(af[mt], hWBase + (uint32_t)(mt * 16 * NSTR + k0) * 2);
#pragma unroll
                for (int n2 = 0; n2 < 2; n2++)
                    ldm4(bq[n2], bBase + (uint32_t)(n2 * 16 * NSTR + k0) * 2);
#pragma unroll
                for (int mt = 0; mt < 2; mt++)
#pragma unroll
                    for (int n2 = 0; n2 < 2; n2++) {
                        mma16816(acc2[mt][2 * n2], af[mt], bq[n2]);
                        mma16816(acc2[mt][2 * n2 + 1], af[mt], bq[n2] + 2);
                    }
            }
        }
        __syncthreads();
    }

    // epilogue: bias2 + residual (x2 re-read, L2-hot), fp32 out
#pragma unroll
    for (int mt = 0; mt < 2; mt++) {
        int row = m0 + wm * 32 + mt * 16 + gid;
#pragma unroll
        for (int nt = 0; nt < 4; nt++) {
            int col = wn * 32 + nt * 8 + tig * 2;
            float bb0 = b2[col], bb1 = b2[col + 1];
            size_t o0 = (size_t)row * CC + col;
            size_t o1 = (size_t)(row + 8) * CC + col;
            float2 r0 = *(const float2*)(x2 + o0);
            float2 r1 = *(const float2*)(x2 + o1);
            *(float2*)(out + o0) = make_float2(acc2[mt][nt][0] + bb0 + r0.x,
                                              acc2[mt][nt][1] + bb1 + r0.y);
            *(float2*)(out + o1) = make_float2(acc2[mt][nt][2] + bb0 + r1.x,
                                              acc2[mt][nt][3] + bb1 + r1.y);
        }
    }
}

// ---------------------------------------------------------------------------
// HMMA attention (R13 form): 224 threads, register-resident P, ldmatrix,
// combined bf16 bias+mask table.
// ---------------------------------------------------------------------------
#define QSTR 40
#define PSTR 120
#define ASMEM_ELEMS (2 * 112 * QSTR + 32 * PSTR)

__global__ __launch_bounds__(224) void attn_mma_kernel(
        const __nv_bfloat16* __restrict__ qkv, __nv_bfloat16* __restrict__ out) {
    extern __shared__ __align__(16) __nv_bfloat16 asmem[];
    __nv_bfloat16* sQ  = asmem;
    __nv_bfloat16* sK  = sQ + 112 * QSTR;
    __nv_bfloat16* sVt = sK + 112 * QSTR;

    int bwin = blockIdx.x >> 2, head = blockIdx.x & 3;
    int tid = threadIdx.x, warp = tid >> 5, lane = tid & 31;
    int gid = lane >> 2, tig = lane & 3;
    int lr8 = lane & 7, lm = lane >> 3;

    size_t base = (size_t)bwin * NTOK * 384 + head * 32;
#pragma unroll
    for (int it = 0; it < 7; it++) {
        int idx = tid + it * 224;
        int n = idx >> 4, d2 = (idx & 15) << 1;
        size_t o = base + (size_t)n * 384 + d2;
        *(uint32_t*)&sQ[n * QSTR + d2] = *(const uint32_t*)(qkv + o);
        *(uint32_t*)&sK[n * QSTR + d2] = *(const uint32_t*)(qkv + o + 128);
    }
#pragma unroll
    for (int it = 0; it < 14; it++) {
        int idx = tid + it * 224;
        int n = idx >> 5, d = idx & 31;
        sVt[d * PSTR + n] = qkv[base + (size_t)n * 384 + 256 + d];
    }
    {
        int idx = tid;
        int r = 98 + (idx >> 4), d2 = (idx & 15) << 1;
        *(uint32_t*)&sQ[r * QSTR + d2] = 0u;
        *(uint32_t*)&sK[r * QSTR + d2] = 0u;
    }
#pragma unroll
    for (int it = 0; it < 2; it++) {
        int idx = tid + it * 224;
        int d = idx / 14, n = 98 + idx % 14;
        sVt[d * PSTR + n] = __float2bfloat16(0.f);
    }
    __syncthreads();

    int mrow = warp << 4;
    float acc[14][4];
#pragma unroll
    for (int n = 0; n < 14; n++)
#pragma unroll
        for (int e = 0; e < 4; e++) acc[n][e] = 0.f;

    uint32_t qBase = su32(sQ) + (uint32_t)((mrow + lr8 + (lm & 1) * 8) * QSTR
                                           + (lm >> 1) * 8) * 2;
    uint32_t kBase = su32(sK) + (uint32_t)((lr8 + (lm >> 1) * 8) * QSTR
                                           + (lm & 1) * 8) * 2;

#pragma unroll
    for (int ks = 0; ks < 2; ks++) {
        int k0 = ks << 4;
        uint32_t af[4];
        ldm4(af, qBase + (uint32_t)k0 * 2);
#pragma unroll
        for (int n2 = 0; n2 < 7; n2++) {
            uint32_t bq[4];
            ldm4(bq, kBase + (uint32_t)(n2 * 16 * QSTR + k0) * 2);
            mma16816(acc[2 * n2], af, bq);
            mma16816(acc[2 * n2 + 1], af, bq + 2);
        }
    }

    int win = bwin & 255;
    int cls = ((win >> 6) == 3 ? 4 : 0) + (((win >> 3) & 7) == 7 ? 2 : 0)
            + ((win & 7) == 7 ? 1 : 0);
    const __nv_bfloat16* bm = g_biasMask + (size_t)(cls * 4 + head) * 12544;

    int r0 = mrow + gid, r1 = r0 + 8;
    float mx0 = -1e30f, mx1 = -1e30f;
#pragma unroll
    for (int n = 0; n < 14; n++) {
        int col = n * 8 + tig * 2;
        float2 b0 = __bfloat1622float2(*(const __nv_bfloat162*)(bm + r0 * 112 + col));
        float2 b1 = __bfloat1622float2(*(const __nv_bfloat162*)(bm + r1 * 112 + col));
        acc[n][0] = acc[n][0] * SCALE + b0.x;
        acc[n][1] = acc[n][1] * SCALE + b0.y;
        acc[n][2] = acc[n][2] * SCALE + b1.x;
        acc[n][3] = acc[n][3] * SCALE + b1.y;
        if (col < 98)     { mx0 = fmaxf(mx0, acc[n][0]); mx1 = fmaxf(mx1, acc[n][2]); }
        if (col + 1 < 98) { mx0 = fmaxf(mx0, acc[n][1]); mx1 = fmaxf(mx1, acc[n][3]); }
    }
    mx0 = fmaxf(mx0, __shfl_xor_sync(0xffffffffu, mx0, 1));
    mx0 = fmaxf(mx0, __shfl_xor_sync(0xffffffffu, mx0, 2));
    mx1 = fmaxf(mx1, __shfl_xor_sync(0xffffffffu, mx1, 1));
    mx1 = fmaxf(mx1, __shfl_xor_sync(0xffffffffu, mx1, 2));
    float sm0 = 0.f, sm1 = 0.f;
#pragma unroll
    for (int n = 0; n < 14; n++) {
        int col = n * 8 + tig * 2;
        float e0 = (col < 98)     ? __expf(acc[n][0] - mx0) : 0.f;
        float e1 = (col + 1 < 98) ? __expf(acc[n][1] - mx0) : 0.f;
        float e2 = (col < 98)     ? __expf(acc[n][2] - mx1) : 0.f;
        float e3 = (col + 1 < 98) ? __expf(acc[n][3] - mx1) : 0.f;
        acc[n][0] = e0; acc[n][1] = e1; acc[n][2] = e2; acc[n][3] = e3;
        sm0 += e0 + e1; sm1 += e2 + e3;
    }
    sm0 += __shfl_xor_sync(0xffffffffu, sm0, 1);
    sm0 += __shfl_xor_sync(0xffffffffu, sm0, 2);
    sm1 += __shfl_xor_sync(0xffffffffu, sm1, 1);
    sm1 += __shfl_xor_sync(0xffffffffu, sm1, 2);
    float inv0 = 1.f / sm0, inv1 = 1.f / sm1;

    uint32_t plo[14], phi[14];
#pragma unroll
    for (int n = 0; n < 14; n++) {
        plo[n] = packbf2(acc[n][0] * inv0, acc[n][1] * inv0);
        phi[n] = packbf2(acc[n][2] * inv1, acc[n][3] * inv1);
    }

    uint32_t vBase = su32(sVt) + (uint32_t)((lr8 + (lm >> 1) * 8) * PSTR
                                            + (lm & 1) * 8) * 2;
    float oacc[4][4];
#pragma unroll
    for (int n = 0; n < 4; n++)
#pragma unroll
        for (int e = 0; e < 4; e++) oacc[n][e] = 0.f;
#pragma unroll
    for (int ks = 0; ks < 7; ks++) {
        int k0 = ks << 4;
        uint32_t af[4];
        af[0] = plo[2 * ks];
        af[1] = phi[2 * ks];
        af[2] = plo[2 * ks + 1];
        af[3] = phi[2 * ks + 1];
#pragma unroll
        for (int n2 = 0; n2 < 2; n2++) {
            uint32_t bq[4];
            ldm4(bq, vBase + (uint32_t)(n2 * 16 * PSTR + k0) * 2);
            mma16816(oacc[2 * n2], af, bq);
            mma16816(oacc[2 * n2 + 1], af, bq + 2);
        }
    }
    size_t obase = (size_t)bwin * NTOK * CC + head * 32;
#pragma unroll
    for (int n = 0; n < 4; n++) {
        int col = n * 8 + tig * 2;
        if (r0 < 98)
            *(__nv_bfloat162*)(out + obase + (size_t)r0 * CC + col) =
                __floats2bfloat162_rn(oacc[n][0], oacc[n][1]);
        if (r1 < 98)
            *(__nv_bfloat162*)(out + obase + (size_t)r1 * CC + col) =
                __floats2bfloat162_rn(oacc[n][2], oacc[n][3]);
    }
}

// ---------------------------------------------------------------------------
// Launch
// ---------------------------------------------------------------------------
extern "C" void kernel_launch(void* const* d_in, const int* in_sizes, int n_in,
                              void* d_out, int out_size) {
    const float* x       = (const float*)d_in[0];
    const float* norm1_g = (const float*)d_in[1];
    const float* norm1_b = (const float*)d_in[2];
    const float* qkv_w   = (const float*)d_in[3];
    const float* qkv_b   = (const float*)d_in[4];
    const float* proj_w  = (const float*)d_in[5];
    const float* proj_b  = (const float*)d_in[6];
    const float* rpb     = (const float*)d_in[7];
    const float* norm2_g = (const float*)d_in[8];
    const float* norm2_b = (const float*)d_in[9];
    const float* fc1_w   = (const float*)d_in[10];
    const float* fc1_b   = (const float*)d_in[11];
    const float* fc2_w   = (const float*)d_in[12];
    const float* fc2_b   = (const float*)d_in[13];
    float* outp = (float*)d_out;

    __nv_bfloat16 *bh1, *bh2, *wt;
    float *bufB;
    cudaGetSymbolAddress((void**)&bh1, g_bh1);
    cudaGetSymbolAddress((void**)&bh2, g_bh2);
    cudaGetSymbolAddress((void**)&wt, g_wt);
    cudaGetSymbolAddress((void**)&bufB, g_bufB);

    cudaFuncSetAttribute(attn_mma_kernel, cudaFuncAttributeMaxDynamicSharedMemorySize,
                         ASMEM_ELEMS * 2);
    cudaFuncSetAttribute(lnqkv_kernel,
                         cudaFuncAttributeMaxDynamicSharedMemorySize, NL_SMEM);
    cudaFuncSetAttribute(ffn_kernel,
                         cudaFuncAttributeMaxDynamicSharedMemorySize, FF_SMEM);

    // combined prep (weights + bias/mask table)
    prep_kernel<<<(PREP_TOTAL + 255) / 256, 256>>>(qkv_w, proj_w, fc1_w, fc2_w, rpb);

    // fused LN1 + gather + QKV GEMM -> bh1 bf16 [M,384]
    lnqkv_kernel<<<MROWS / 128, 256, NL_SMEM>>>(
        x, norm1_g, norm1_b, wt + WT_QKV, qkv_b, bh1);

    // attention -> bh2 bf16 (window layout)
    attn_mma_kernel<<<BWIN * 4, 224, ASMEM_ELEMS * 2>>>(bh1, bh2);

    // proj GEMM fused with scatter + residual -> bufB (x2, token layout)
    proj_fused_kernel<<<MROWS / 128, 256, GEMM_SMEM>>>(
        bh2, wt + WT_PROJ, proj_b, x, bufB);

    // fused LN2 + FFN -> d_out fp32
    ffn_kernel<<<MROWS / 64, 256, FF_SMEM>>>(
        bufB, norm2_g, norm2_b, wt + WT_FC1, wt + WT_FC2, fc1_b, fc2_b, outp);
}

// round 17
// speedup vs baseline: 1.0618x; 1.0618x over previous
#include <cuda_runtime.h>
#include <cuda_bf16.h>
#include <math.h>
#include <stdint.h>

// ---------------------------------------------------------------------------
// Problem constants
// ---------------------------------------------------------------------------
#define CC 128
#define NTOK 98
#define BWIN 2048
#define LTOK 25088
#define MROWS 200704
#define HID 512
#define SCALE 0.17677669529663687f
#define EPS 1e-5f

// ---------------------------------------------------------------------------
// Scratch
// ---------------------------------------------------------------------------
__device__ __nv_bfloat16 g_bh1[(size_t)MROWS * 384];  // qkv out
__device__ __nv_bfloat16 g_bh2[(size_t)MROWS * CC];   // attn out (window layout)
__device__ __nv_bfloat16 g_bh3[(size_t)MROWS * CC];   // ln2 out (token layout)
__device__ float g_bufB[(size_t)MROWS * CC];          // x2 residual (token layout)
__device__ __nv_bfloat16 g_biasMask[32 * 112 * 112];  // combined bias+mask, bf16
__device__ __nv_bfloat16 g_wt[196608];                // transposed bf16 weights [N][K]

#define WT_QKV 0        // 384 x 128
#define WT_PROJ 49152   // 128 x 128
#define WT_FC1 65536    // 512 x 128
#define WT_FC2 131072   // 128 x 512

// ---------------------------------------------------------------------------
// HMMA + ldmatrix helpers (baseline PTX, sm_75/80+)
// ---------------------------------------------------------------------------
__device__ __forceinline__ void mma16816(float* c, const uint32_t* a, const uint32_t* b) {
    asm volatile(
        "mma.sync.aligned.m16n8k16.row.col.f32.bf16.bf16.f32 "
        "{%0,%1,%2,%3}, {%4,%5,%6,%7}, {%8,%9}, {%0,%1,%2,%3};"
        : "+f"(c[0]), "+f"(c[1]), "+f"(c[2]), "+f"(c[3])
        : "r"(a[0]), "r"(a[1]), "r"(a[2]), "r"(a[3]), "r"(b[0]), "r"(b[1]));
}
__device__ __forceinline__ uint32_t su32(const void* p) {
    return (uint32_t)__cvta_generic_to_shared(p);
}
__device__ __forceinline__ void ldm4(uint32_t* r, uint32_t addr) {
    asm volatile("ldmatrix.sync.aligned.m8n8.x4.shared.b16 {%0,%1,%2,%3}, [%4];"
                 : "=r"(r[0]), "=r"(r[1]), "=r"(r[2]), "=r"(r[3]) : "r"(addr));
}
__device__ __forceinline__ void ldm4t(uint32_t* r, uint32_t addr) {
    asm volatile("ldmatrix.sync.aligned.m8n8.x4.trans.shared.b16 {%0,%1,%2,%3}, [%4];"
                 : "=r"(r[0]), "=r"(r[1]), "=r"(r[2]), "=r"(r[3]) : "r"(addr));
}

// cp.async 16B
__device__ __forceinline__ void cp16(void* sdst, const void* gsrc) {
    uint32_t sa = (uint32_t)__cvta_generic_to_shared(sdst);
    asm volatile("cp.async.cg.shared.global [%0], [%1], 16;" :: "r"(sa), "l"(gsrc));
}
__device__ __forceinline__ void cp_commit() {
    asm volatile("cp.async.commit_group;");
}
template <int N>
__device__ __forceinline__ void cp_wait() {
    asm volatile("cp.async.wait_group %0;" :: "n"(N));
}

__device__ __forceinline__ uint32_t packbf2(float a, float b) {
    __nv_bfloat162 t = __floats2bfloat162_rn(a, b);
    return *(uint32_t*)&t;
}
__device__ __forceinline__ float gelu1(float v) {
    return 0.5f * v * (1.0f + erff(v * 0.7071067811865475f));
}

// ---------------------------------------------------------------------------
// Combined prep: weight transposes + combined bias/mask table.
// ---------------------------------------------------------------------------
#define PREP_QKV_END  49152
#define PREP_PROJ_END 65536
#define PREP_FC1_END  131072
#define PREP_FC2_END  196608
#define PREP_TOTAL    (196608 + 32 * 112 * 112)

__device__ __forceinline__ int regid(int tok, int tb, int hb, int wb) {
    int t0 = tok / 49, r = tok % 49, h0 = r / 7, w0 = r % 7;
    int rt = tb ? (t0 == 0 ? 1 : 2) : 0;
    int rh = hb ? (h0 < 4 ? 1 : 2) : 0;
    int rw = wb ? (w0 < 4 ? 1 : 2) : 0;
    return rt * 9 + rh * 3 + rw;
}

__global__ void prep_kernel(const float* __restrict__ qkv_w,
                            const float* __restrict__ proj_w,
                            const float* __restrict__ fc1_w,
                            const float* __restrict__ fc2_w,
                            const float* __restrict__ rpb) {
    int idx = blockIdx.x * blockDim.x + threadIdx.x;
    if (idx >= PREP_TOTAL) return;
    if (idx < PREP_QKV_END) {
        int l = idx; int k = l / 384, n = l % 384;
        g_wt[WT_QKV + n * 128 + k] = __float2bfloat16(qkv_w[l]);
    } else if (idx < PREP_PROJ_END) {
        int l = idx - PREP_QKV_END; int k = l / 128, n = l % 128;
        g_wt[WT_PROJ + n * 128 + k] = __float2bfloat16(proj_w[l]);
    } else if (idx < PREP_FC1_END) {
        int l = idx - PREP_PROJ_END; int k = l / 512, n = l % 512;
        g_wt[WT_FC1 + n * 128 + k] = __float2bfloat16(fc1_w[l]);
    } else if (idx < PREP_FC2_END) {
        int l = idx - PREP_FC1_END; int k = l / 128, n = l % 128;
        g_wt[WT_FC2 + n * 512 + k] = __float2bfloat16(fc2_w[l]);
    } else {
        int m = idx - PREP_FC2_END;
        int cls = m / 50176;
        int rem = m % 50176;
        int h = rem / 12544;
        int rr = rem % 12544;
        int i = rr / 112, j = rr % 112;
        float v = 0.f;
        if (i < NTOK && j < NTOK) {
            int ti = i / 49, hi = (i / 7) % 7, wi = i % 7;
            int tj = j / 49, hj = (j / 7) % 7, wj = j % 7;
            int ridx = (ti - tj + 1) * 169 + (hi - hj + 6) * 13 + (wi - wj + 6);
            v = rpb[ridx * 4 + h];
            int tb = (cls >> 2) & 1, hb = (cls >> 1) & 1, wb = cls & 1;
            if (regid(i, tb, hb, wb) != regid(j, tb, hb, wb)) v += -100.f;
        }
        g_biasMask[m] = __float2bfloat16(v);
    }
}

// window-layout row -> token row (shift/roll gather mapping)
__device__ __forceinline__ int win2tok(int row) {
    int bwin = row / NTOK, n = row % NTOK;
    int b = bwin >> 8, win = bwin & 255;
    int tw = win >> 6, hw = (win >> 3) & 7, ww = win & 7;
    int t0 = n / 49, r49 = n % 49, h0 = r49 / 7, w0 = r49 % 7;
    int tg = (tw * 2 + t0 + 1) & 7;
    int hg = hw * 7 + h0 + 3; if (hg >= 56) hg -= 56;
    int wg = ww * 7 + w0 + 3; if (wg >= 56) wg -= 56;
    return b * LTOK + (tg * 56 + hg) * 56 + wg;
}

// ---------------------------------------------------------------------------
// Fused LN1 + shift/window-gather + QKV GEMM (A resident, 3 n-tiles)
// ---------------------------------------------------------------------------
#define NSTR 136
#define NL_TILE_BYTES (128 * NSTR * 2)
#define NL_SMEM (3 * NL_TILE_BYTES)

__global__ __launch_bounds__(256) void lnqkv_kernel(
        const float* __restrict__ x, const float* __restrict__ lng,
        const float* __restrict__ lnb, const __nv_bfloat16* __restrict__ Wt,
        const float* __restrict__ bias, __nv_bfloat16* __restrict__ out) {
    extern __shared__ __align__(16) char smem[];
    __nv_bfloat16* sA = (__nv_bfloat16*)smem;

    int t = threadIdx.x;
    int warp = t >> 5, lane = t & 31;
    int wm = warp & 1, wn = warp >> 1;
    int gid = lane >> 2, tig = lane & 3;
    int lr8 = lane & 7, lm = lane >> 3;
    int m0 = blockIdx.x << 7;
    const int NT = 3, Np = 384;

    {
        __nv_bfloat16* sB0 = (__nv_bfloat16*)(smem + NL_TILE_BYTES);
#pragma unroll
        for (int it = 0; it < 8; it++) {
            int c = t + (it << 8);
            int r = c >> 4, c8 = (c & 15) << 3;
            cp16(&sB0[r * NSTR + c8], Wt + (size_t)r * 128 + c8);
        }
        cp_commit();
    }

    // LN1 + gather into sA
    {
        float4 gv = *(const float4*)(lng + lane * 4);
        float4 bv = *(const float4*)(lnb + lane * 4);
#pragma unroll
        for (int i = 0; i < 16; i++) {
            int row = warp * 16 + i;
            int tok = win2tok(m0 + row);
            float4 v = *(const float4*)(x + (size_t)tok * CC + lane * 4);
            float s = v.x + v.y + v.z + v.w;
#pragma unroll
            for (int o = 16; o > 0; o >>= 1) s += __shfl_xor_sync(0xffffffffu, s, o);
            float mean = s * (1.0f / CC);
            float dx = v.x - mean, dy = v.y - mean, dz = v.z - mean, dw = v.w - mean;
            float q = dx * dx + dy * dy + dz * dz + dw * dw;
#pragma unroll
            for (int o = 16; o > 0; o >>= 1) q += __shfl_xor_sync(0xffffffffu, q, o);
            float rstd = rsqrtf(q * (1.0f / CC) + EPS);
            uint32_t p0 = packbf2(dx * rstd * gv.x + bv.x, dy * rstd * gv.y + bv.y);
            uint32_t p1 = packbf2(dz * rstd * gv.z + bv.z, dw * rstd * gv.w + bv.w);
            *(uint2*)&sA[row * NSTR + lane * 4] = make_uint2(p0, p1);
        }
    }

    uint32_t aBase = su32(sA) + (uint32_t)((wm * 64 + lr8 + (lm & 1) * 8) * NSTR
                                           + (lm >> 1) * 8) * 2;

    for (int nt = 0; nt < NT; nt++) {
        if (nt + 1 < NT) {
            __nv_bfloat16* sBn = (__nv_bfloat16*)(smem + NL_TILE_BYTES
                                                  + ((nt + 1) & 1) * NL_TILE_BYTES);
            const __nv_bfloat16* Bg = Wt + (size_t)(nt + 1) * 128 * 128;
#pragma unroll
            for (int it = 0; it < 8; it++) {
                int c = t + (it << 8);
                int r = c >> 4, c8 = (c & 15) << 3;
                cp16(&sBn[r * NSTR + c8], Bg + (size_t)r * 128 + c8);
            }
            cp_commit();
            cp_wait<1>();
        } else {
            cp_wait<0>();
        }
        __syncthreads();
        const __nv_bfloat16* sB = (const __nv_bfloat16*)(smem + NL_TILE_BYTES
                                                         + (nt & 1) * NL_TILE_BYTES);
        uint32_t bBase = su32(sB) + (uint32_t)((wn * 32 + lr8 + (lm >> 1) * 8) * NSTR
                                               + (lm & 1) * 8) * 2;
        float acc[4][4][4];
#pragma unroll
        for (int mt = 0; mt < 4; mt++)
#pragma unroll
            for (int ntx = 0; ntx < 4; ntx++)
#pragma unroll
                for (int e = 0; e < 4; e++) acc[mt][ntx][e] = 0.f;

#pragma unroll
        for (int ks = 0; ks < 8; ks++) {
            int k0 = ks << 4;
            uint32_t af[4][4], bq[2][4];
#pragma unroll
            for (int mt = 0; mt < 4; mt++)
                ldm4(af[mt], aBase + (uint32_t)(mt * 16 * NSTR + k0) * 2);
#pragma unroll
            for (int n2 = 0; n2 < 2; n2++)
                ldm4(bq[n2], bBase + (uint32_t)(n2 * 16 * NSTR + k0) * 2);
#pragma unroll
            for (int mt = 0; mt < 4; mt++)
#pragma unroll
                for (int n2 = 0; n2 < 2; n2++) {
                    mma16816(acc[mt][2 * n2], af[mt], bq[n2]);
                    mma16816(acc[mt][2 * n2 + 1], af[mt], bq[n2] + 2);
                }
        }
        __syncthreads();

        int ncol0 = nt * 128;
#pragma unroll
        for (int mt = 0; mt < 4; mt++) {
            int row = m0 + wm * 64 + mt * 16 + gid;
#pragma unroll
            for (int ntx = 0; ntx < 4; ntx++) {
                int col = ncol0 + wn * 32 + ntx * 8 + tig * 2;
                float b0 = bias[col], b1 = bias[col + 1];
                *(__nv_bfloat162*)(out + (size_t)row * Np + col) =
                    __floats2bfloat162_rn(acc[mt][ntx][0] + b0, acc[mt][ntx][1] + b1);
                *(__nv_bfloat162*)(out + (size_t)(row + 8) * Np + col) =
                    __floats2bfloat162_rn(acc[mt][ntx][2] + b0, acc[mt][ntx][3] + b1);
            }
        }
    }
}

// ---------------------------------------------------------------------------
// Proj GEMM (BK=32 double-buffered, K=128) fused with scatter+resid+LN2.
// Two-phase 64-row epilogue spill keeps smem at 40KB -> 2 CTAs/SM.
// ---------------------------------------------------------------------------
#define SSTR 40
#define STAGE_BYTES (2 * 128 * SSTR * 2)
#define GEMM_SMEM   (2 * STAGE_BYTES)      // 40960

__global__ __launch_bounds__(256) void proj_fused_kernel(
        const __nv_bfloat16* __restrict__ A, const __nv_bfloat16* __restrict__ Wt,
        const float* __restrict__ bias, __nv_bfloat16* __restrict__ lnout,
        const float* __restrict__ xres, const float* __restrict__ ln_g,
        const float* __restrict__ ln_b, float* __restrict__ x2out) {
    extern __shared__ __align__(16) char smem[];
    const int K = 128;

    int t = threadIdx.x;
    int warp = t >> 5, lane = t & 31;
    int wm = warp & 1, wn = warp >> 1;
    int gid = lane >> 2, tig = lane & 3;
    int lr8 = lane & 7, lm = lane >> 3;
    int m0 = blockIdx.x << 7;

    float acc[4][4][4];
#pragma unroll
    for (int mt = 0; mt < 4; mt++)
#pragma unroll
        for (int nt = 0; nt < 4; nt++)
#pragma unroll
            for (int e = 0; e < 4; e++) acc[mt][nt][e] = 0.f;

    int lr = t >> 2;
    int lc = (t & 3) << 3;

    const __nv_bfloat16* Ag = A + (size_t)(m0 + lr) * K + lc;
    const __nv_bfloat16* Bg = Wt + (size_t)lr * K + lc;
    int sa0 = (lr * SSTR + lc) * 2;
    int sa1 = ((lr + 64) * SSTR + lc) * 2;

    uint32_t aOff = (uint32_t)((wm * 64 + lr8 + (lm & 1) * 8) * SSTR + (lm >> 1) * 8) * 2;
    uint32_t bOff = (uint32_t)((wn * 32 + lr8 + (lm >> 1) * 8) * SSTR + (lm & 1) * 8) * 2
                    + 128 * SSTR * 2;

    {
        char* st = smem;
        cp16(st + sa0, Ag);
        cp16(st + sa1, Ag + (size_t)64 * K);
        cp16(st + 10240 + sa0, Bg);
        cp16(st + 10240 + sa1, Bg + (size_t)64 * K);
        cp_commit();
    }

    for (int kc = 0; kc < 4; kc++) {
        if (kc + 1 < 4) {
            char* st = smem + ((kc + 1) & 1) * STAGE_BYTES;
            int kt = (kc + 1) << 5;
            cp16(st + sa0, Ag + kt);
            cp16(st + sa1, Ag + (size_t)64 * K + kt);
            cp16(st + 10240 + sa0, Bg + kt);
            cp16(st + 10240 + sa1, Bg + (size_t)64 * K + kt);
            cp_commit();
            cp_wait<1>();
        } else {
            cp_wait<0>();
        }
        __syncthreads();
        uint32_t stageu = su32(smem) + (uint32_t)((kc & 1) * STAGE_BYTES);
#pragma unroll
        for (int ks = 0; ks < 2; ks++) {
            int k0 = ks << 4;
            uint32_t af[4][4], bq[2][4];
#pragma unroll
            for (int mt = 0; mt < 4; mt++)
                ldm4(af[mt], stageu + aOff + (uint32_t)(mt * 16 * SSTR + k0) * 2);
#pragma unroll
            for (int n2 = 0; n2 < 2; n2++)
                ldm4(bq[n2], stageu + bOff + (uint32_t)(n2 * 16 * SSTR + k0) * 2);
#pragma unroll
            for (int mt = 0; mt < 4; mt++)
#pragma unroll
                for (int n2 = 0; n2 < 2; n2++) {
                    mma16816(acc[mt][2 * n2], af[mt], bq[n2]);
                    mma16816(acc[mt][2 * n2 + 1], af[mt], bq[n2] + 2);
                }
        }
        __syncthreads();
    }

    // two-phase epilogue: spill + scatter/resid/LN2 per 64-row half
    float* sout = (float*)smem;   // 64 x 132 fp32 = 33792 B
#pragma unroll
    for (int ph = 0; ph < 2; ph++) {
        if (wm == ph) {
#pragma unroll
            for (int mt = 0; mt < 4; mt++) {
                int row = mt * 16 + gid;
#pragma unroll
                for (int nt = 0; nt < 4; nt++) {
                    int col = wn * 32 + nt * 8 + tig * 2;
                    float b0 = bias[col], b1 = bias[col + 1];
                    sout[row * 132 + col] = acc[mt][nt][0] + b0;
                    sout[row * 132 + col + 1] = acc[mt][nt][1] + b1;
                    sout[(row + 8) * 132 + col] = acc[mt][nt][2] + b0;
                    sout[(row + 8) * 132 + col + 1] = acc[mt][nt][3] + b1;
                }
            }
        }
        __syncthreads();
#pragma unroll
        for (int i = 0; i < 8; i++) {
            int row = warp * 8 + i;
            int tr = win2tok(m0 + ph * 64 + row);
            const float* xr = xres + (size_t)tr * CC;
            float v[4]; float s = 0.f;
#pragma unroll
            for (int k = 0; k < 4; k++) {
                int c = lane + 32 * k;
                v[k] = sout[row * 132 + c] + xr[c];
                s += v[k];
            }
            float* dx2 = x2out + (size_t)tr * CC;
#pragma unroll
            for (int k = 0; k < 4; k++) dx2[lane + 32 * k] = v[k];
#pragma unroll
            for (int o = 16; o > 0; o >>= 1) s += __shfl_xor_sync(0xffffffffu, s, o);
            float mean = s * (1.0f / CC);
            float q = 0.f;
#pragma unroll
            for (int k = 0; k < 4; k++) { float d = v[k] - mean; q += d * d; }
#pragma unroll
            for (int o = 16; o > 0; o >>= 1) q += __shfl_xor_sync(0xffffffffu, q, o);
            float rstd = rsqrtf(q * (1.0f / CC) + EPS);
            __nv_bfloat16* dst = lnout + (size_t)tr * CC;
#pragma unroll
            for (int k = 0; k < 4; k++) {
                int c = lane + 32 * k;
                dst[c] = __float2bfloat16((v[k] - mean) * rstd * ln_g[c] + ln_b[c]);
            }
        }
        __syncthreads();
    }
}

// ---------------------------------------------------------------------------
// Fused FFN, interleaved (64-row CTA, 2 CTAs/SM)
// ---------------------------------------------------------------------------
#define FF_SA_BYTES (64 * NSTR * 2)
#define FF_SH_BYTES (64 * NSTR * 2)
#define FF_SB_BYTES (128 * NSTR * 2)
#define FF_SMEM (FF_SA_BYTES + FF_SH_BYTES + 2 * FF_SB_BYTES)

__global__ __launch_bounds__(256) void ffn_kernel(
        const __nv_bfloat16* __restrict__ A,
        const __nv_bfloat16* __restrict__ w1,
        const __nv_bfloat16* __restrict__ w2,
        const float* __restrict__ b1, const float* __restrict__ b2,
        const float* __restrict__ resid, float* __restrict__ out) {
    extern __shared__ __align__(16) char smem[];
    __nv_bfloat16* sA = (__nv_bfloat16*)smem;
    __nv_bfloat16* sH = (__nv_bfloat16*)(smem + FF_SA_BYTES);
    char* sBbase = smem + FF_SA_BYTES + FF_SH_BYTES;

    int t = threadIdx.x;
    int warp = t >> 5, lane = t & 31;
    int wm = warp & 1, wn = warp >> 1;
    int gid = lane >> 2, tig = lane & 3;
    int lr8 = lane & 7, lm = lane >> 3;
    int m0 = blockIdx.x << 6;

    {
        const __nv_bfloat16* Ag = A + (size_t)m0 * 128;
#pragma unroll
        for (int it = 0; it < 4; it++) {
            int c = t + (it << 8);
            int r = c >> 4, c8 = (c & 15) << 3;
            cp16(&sA[r * NSTR + c8], Ag + (size_t)r * 128 + c8);
        }
        __nv_bfloat16* sB0 = (__nv_bfloat16*)sBbase;
#pragma unroll
        for (int it = 0; it < 8; it++) {
            int c = t + (it << 8);
            int r = c >> 4, c8 = (c & 15) << 3;
            cp16(&sB0[r * NSTR + c8], w1 + (size_t)r * 128 + c8);
        }
        cp_commit();
    }

    uint32_t aBase = su32(sA) + (uint32_t)((wm * 32 + lr8 + (lm & 1) * 8) * NSTR
                                           + (lm >> 1) * 8) * 2;
    uint32_t hWBase = su32(sH) + (uint32_t)((wm * 32 + lr8 + (lm & 1) * 8) * NSTR
                                            + (lm >> 1) * 8) * 2;

    float acc2[2][4][4];
#pragma unroll
    for (int mt = 0; mt < 2; mt++)
#pragma unroll
        for (int nt = 0; nt < 4; nt++)
#pragma unroll
            for (int e = 0; e < 4; e++) acc2[mt][nt][e] = 0.f;

    for (int j = 0; j < 8; j++) {
        if (j + 1 < 8) {
            __nv_bfloat16* sBn = (__nv_bfloat16*)(sBbase + ((j + 1) & 1) * FF_SB_BYTES);
            int jn = j + 1;
            if ((jn & 1) == 0) {
                const __nv_bfloat16* Bg = w1 + (size_t)(jn >> 1) * 128 * 128;
#pragma unroll
                for (int it = 0; it < 8; it++) {
                    int c = t + (it << 8);
                    int r = c >> 4, c8 = (c & 15) << 3;
                    cp16(&sBn[r * NSTR + c8], Bg + (size_t)r * 128 + c8);
                }
            } else {
                const __nv_bfloat16* Bg = w2 + (size_t)(jn >> 1) * 128;
#pragma unroll
                for (int it = 0; it < 8; it++) {
                    int c = t + (it << 8);
                    int r = c >> 4, c8 = (c & 15) << 3;
                    cp16(&sBn[r * NSTR + c8], Bg + (size_t)r * 512 + c8);
                }
            }
            cp_commit();
            cp_wait<1>();
        } else {
            cp_wait<0>();
        }
        __syncthreads();
        const __nv_bfloat16* sB = (const __nv_bfloat16*)(sBbase + (j & 1) * FF_SB_BYTES);
        uint32_t bBase = su32(sB) + (uint32_t)((wn * 32 + lr8 + (lm >> 1) * 8) * NSTR
                                               + (lm & 1) * 8) * 2;

        if ((j & 1) == 0) {
            float acc[2][4][4];
#pragma unroll
            for (int mt = 0; mt < 2; mt++)
#pragma unroll
                for (int nt = 0; nt < 4; nt++)
#pragma unroll
                    for (int e = 0; e < 4; e++) acc[mt][nt][e] = 0.f;
#pragma unroll
            for (int ks = 0; ks < 8; ks++) {
                int k0 = ks << 4;
                uint32_t af[2][4], bq[2][4];
#pragma unroll
                for (int mt = 0; mt < 2; mt++)
                    ldm4(af[mt], aBase + (uint32_t)(mt * 16 * NSTR + k0) * 2);
#pragma unroll
                for (int n2 = 0; n2 < 2; n2++)
                    ldm4(bq[n2], bBase + (uint32_t)(n2 * 16 * NSTR + k0) * 2);
#pragma unroll
                for (int mt = 0; mt < 2; mt++)
#pragma unroll
                    for (int n2 = 0; n2 < 2; n2++) {
                        mma16816(acc[mt][2 * n2], af[mt], bq[n2]);
                        mma16816(acc[mt][2 * n2 + 1], af[mt], bq[n2] + 2);
                    }
            }
            int hc0 = (j >> 1) * 128;
#pragma unroll
            for (int mt = 0; mt < 2; mt++) {
                int row = wm * 32 + mt * 16 + gid;
#pragma unroll
                for (int nt = 0; nt < 4; nt++) {
                    int col = wn * 32 + nt * 8 + tig * 2;
                    float bb0 = b1[hc0 + col], bb1 = b1[hc0 + col + 1];
                    *(uint32_t*)&sH[row * NSTR + col] =
                        packbf2(gelu1(acc[mt][nt][0] + bb0), gelu1(acc[mt][nt][1] + bb1));
                    *(uint32_t*)&sH[(row + 8) * NSTR + col] =
                        packbf2(gelu1(acc[mt][nt][2] + bb0), gelu1(acc[mt][nt][3] + bb1));
                }
            }
        } else {
            // H writes (prev iter) already ordered by the two preceding syncs
#pragma unroll
            for (int ks = 0; ks < 8; ks++) {
                int k0 = ks << 4;
                uint32_t af[2][4], bq[2][4];
#pragma unroll
                for (int mt = 0; mt < 2; mt++)
                    ldm4(af[mt], hWBase + (uint32_t)(mt * 16 * NSTR + k0) * 2);
#pragma unroll
                for (int n2 = 0; n2 < 2; n2++)
                    ldm4(bq[n2], bBase + (uint32_t)(n2 * 16 * NSTR + k0) * 2);
#pragma unroll
                for (int mt = 0; mt < 2; mt++)
#pragma unroll
                    for (int n2 = 0; n2 < 2; n2++) {
                        mma16816(acc2[mt][2 * n2], af[mt], bq[n2]);
                        mma16816(acc2[mt][2 * n2 + 1], af[mt], bq[n2] + 2);
                    }
            }
        }
        __syncthreads();
    }

#pragma unroll
    for (int mt = 0; mt < 2; mt++) {
        int row = m0 + wm * 32 + mt * 16 + gid;
#pragma unroll
        for (int nt = 0; nt < 4; nt++) {
            int col = wn * 32 + nt * 8 + tig * 2;
            float bb0 = b2[col], bb1 = b2[col + 1];
            size_t o0 = (size_t)row * CC + col;
            size_t o1 = (size_t)(row + 8) * CC + col;
            float2 r0 = *(const float2*)(resid + o0);
            float2 r1 = *(const float2*)(resid + o1);
            *(float2*)(out + o0) = make_float2(acc2[mt][nt][0] + bb0 + r0.x,
                                              acc2[mt][nt][1] + bb1 + r0.y);
            *(float2*)(out + o1) = make_float2(acc2[mt][nt][2] + bb0 + r1.x,
                                              acc2[mt][nt][3] + bb1 + r1.y);
        }
    }
}

// ---------------------------------------------------------------------------
// HMMA attention: 224 threads, register-resident P, cp.async fill,
// V row-major + ldmatrix.trans for PV (no scalar transpose).
// ---------------------------------------------------------------------------
#define QSTR 40
#define ASMEM_ELEMS (3 * 112 * QSTR)

__global__ __launch_bounds__(224) void attn_mma_kernel(
        const __nv_bfloat16* __restrict__ qkv, __nv_bfloat16* __restrict__ out) {
    extern __shared__ __align__(16) __nv_bfloat16 asmem[];
    __nv_bfloat16* sQ = asmem;                 // [112][QSTR]
    __nv_bfloat16* sK = sQ + 112 * QSTR;       // [112][QSTR]
    __nv_bfloat16* sV = sK + 112 * QSTR;       // [112][QSTR], rows = token m

    int bwin = blockIdx.x >> 2, head = blockIdx.x & 3;
    int tid = threadIdx.x, warp = tid >> 5, lane = tid & 31;
    int gid = lane >> 2, tig = lane & 3;
    int lr8 = lane & 7, lm = lane >> 3;

    size_t base = (size_t)bwin * NTOK * 384 + head * 32;
    // cp.async fill: 98 rows x {Q,K,V} x 4 chunks of 16B = 1176 copies
    for (int idx = tid; idx < 1176; idx += 224) {
        int n = idx / 12, sub = idx - n * 12;
        int mat = sub >> 2, c = sub & 3;
        const __nv_bfloat16* src = qkv + base + (size_t)n * 384 + mat * 128 + c * 8;
        __nv_bfloat16* dstbuf = (mat == 0) ? sQ : ((mat == 1) ? sK : sV);
        cp16(dstbuf + n * QSTR + c * 8, src);
    }
    cp_commit();
    // zero pad rows 98..111, cols 0..31 (one uint32 per thread per buffer)
    {
        int r = 98 + (tid >> 4), d2 = (tid & 15) << 1;
        *(uint32_t*)&sQ[r * QSTR + d2] = 0u;
        *(uint32_t*)&sK[r * QSTR + d2] = 0u;
        *(uint32_t*)&sV[r * QSTR + d2] = 0u;
    }
    cp_wait<0>();
    __syncthreads();

    int mrow = warp << 4;
    float acc[14][4];
#pragma unroll
    for (int n = 0; n < 14; n++)
#pragma unroll
        for (int e = 0; e < 4; e++) acc[n][e] = 0.f;

    uint32_t qBase = su32(sQ) + (uint32_t)((mrow + lr8 + (lm & 1) * 8) * QSTR
                                           + (lm >> 1) * 8) * 2;
    uint32_t kBase = su32(sK) + (uint32_t)((lr8 + (lm >> 1) * 8) * QSTR
                                           + (lm & 1) * 8) * 2;

#pragma unroll
    for (int ks = 0; ks < 2; ks++) {
        int k0 = ks << 4;
        uint32_t af[4];
        ldm4(af, qBase + (uint32_t)k0 * 2);
#pragma unroll
        for (int n2 = 0; n2 < 7; n2++) {
            uint32_t bq[4];
            ldm4(bq, kBase + (uint32_t)(n2 * 16 * QSTR + k0) * 2);
            mma16816(acc[2 * n2], af, bq);
            mma16816(acc[2 * n2 + 1], af, bq + 2);
        }
    }

    int win = bwin & 255;
    int cls = ((win >> 6) == 3 ? 4 : 0) + (((win >> 3) & 7) == 7 ? 2 : 0)
            + ((win & 7) == 7 ? 1 : 0);
    const __nv_bfloat16* bm = g_biasMask + (size_t)(cls * 4 + head) * 12544;

    int r0 = mrow + gid, r1 = r0 + 8;
    float mx0 = -1e30f, mx1 = -1e30f;
#pragma unroll
    for (int n = 0; n < 14; n++) {
        int col = n * 8 + tig * 2;
        float2 b0 = __bfloat1622float2(*(const __nv_bfloat162*)(bm + r0 * 112 + col));
        float2 b1 = __bfloat1622float2(*(const __nv_bfloat162*)(bm + r1 * 112 + col));
        acc[n][0] = acc[n][0] * SCALE + b0.x;
        acc[n][1] = acc[n][1] * SCALE + b0.y;
        acc[n][2] = acc[n][2] * SCALE + b1.x;
        acc[n][3] = acc[n][3] * SCALE + b1.y;
        if (col < 98)     { mx0 = fmaxf(mx0, acc[n][0]); mx1 = fmaxf(mx1, acc[n][2]); }
        if (col + 1 < 98) { mx0 = fmaxf(mx0, acc[n][1]); mx1 = fmaxf(mx1, acc[n][3]); }
    }
    mx0 = fmaxf(mx0, __shfl_xor_sync(0xffffffffu, mx0, 1));
    mx0 = fmaxf(mx0, __shfl_xor_sync(0xffffffffu, mx0, 2));
    mx1 = fmaxf(mx1, __shfl_xor_sync(0xffffffffu, mx1, 1));
    mx1 = fmaxf(mx1, __shfl_xor_sync(0xffffffffu, mx1, 2));
    float sm0 = 0.f, sm1 = 0.f;
#pragma unroll
    for (int n = 0; n < 14; n++) {
        int col = n * 8 + tig * 2;
        float e0 = (col < 98)     ? __expf(acc[n][0] - mx0) : 0.f;
        float e1 = (col + 1 < 98) ? __expf(acc[n][1] - mx0) : 0.f;
        float e2 = (col < 98)     ? __expf(acc[n][2] - mx1) : 0.f;
        float e3 = (col + 1 < 98) ? __expf(acc[n][3] - mx1) : 0.f;
        acc[n][0] = e0; acc[n][1] = e1; acc[n][2] = e2; acc[n][3] = e3;
        sm0 += e0 + e1; sm1 += e2 + e3;
    }
    sm0 += __shfl_xor_sync(0xffffffffu, sm0, 1);
    sm0 += __shfl_xor_sync(0xffffffffu, sm0, 2);
    sm1 += __shfl_xor_sync(0xffffffffu, sm1, 1);
    sm1 += __shfl_xor_sync(0xffffffffu, sm1, 2);
    float inv0 = 1.f / sm0, inv1 = 1.f / sm1;

    uint32_t plo[14], phi[14];
#pragma unroll
    for (int n = 0; n < 14; n++) {
        plo[n] = packbf2(acc[n][0] * inv0, acc[n][1] * inv0);
        phi[n] = packbf2(acc[n][2] * inv1, acc[n][3] * inv1);
    }

    // PV: B-frags via ldmatrix.trans on row-major V[m][d]
    // lane addr: row m = k0 + (lm&1)*8 + lr8, col d = n2*16 + (lm>>1)*8
    uint32_t vBase = su32(sV) + (uint32_t)(((lm & 1) * 8 + lr8) * QSTR
                                           + (lm >> 1) * 8) * 2;
    float oacc[4][4];
#pragma unroll
    for (int n = 0; n < 4; n++)
#pragma unroll
        for (int e = 0; e < 4; e++) oacc[n][e] = 0.f;
#pragma unroll
    for (int ks = 0; ks < 7; ks++) {
        int k0 = ks << 4;
        uint32_t af[4];
        af[0] = plo[2 * ks];
        af[1] = phi[2 * ks];
        af[2] = plo[2 * ks + 1];
        af[3] = phi[2 * ks + 1];
#pragma unroll
        for (int n2 = 0; n2 < 2; n2++) {
            uint32_t bq[4];
            ldm4t(bq, vBase + (uint32_t)(k0 * QSTR + n2 * 16) * 2);
            mma16816(oacc[2 * n2], af, bq);
            mma16816(oacc[2 * n2 + 1], af, bq + 2);
        }
    }
    size_t obase = (size_t)bwin * NTOK * CC + head * 32;
#pragma unroll
    for (int n = 0; n < 4; n++) {
        int col = n * 8 + tig * 2;
        if (r0 < 98)
            *(__nv_bfloat162*)(out + obase + (size_t)r0 * CC + col) =
                __floats2bfloat162_rn(oacc[n][0], oacc[n][1]);
        if (r1 < 98)
            *(__nv_bfloat162*)(out + obase + (size_t)r1 * CC + col) =
                __floats2bfloat162_rn(oacc[n][2], oacc[n][3]);
    }
}

// ---------------------------------------------------------------------------
// Launch
// ---------------------------------------------------------------------------
extern "C" void kernel_launch(void* const* d_in, const int* in_sizes, int n_in,
                              void* d_out, int out_size) {
    const float* x       = (const float*)d_in[0];
    const float* norm1_g = (const float*)d_in[1];
    const float* norm1_b = (const float*)d_in[2];
    const float* qkv_w   = (const float*)d_in[3];
    const float* qkv_b   = (const float*)d_in[4];
    const float* proj_w  = (const float*)d_in[5];
    const float* proj_b  = (const float*)d_in[6];
    const float* rpb     = (const float*)d_in[7];
    const float* norm2_g = (const float*)d_in[8];
    const float* norm2_b = (const float*)d_in[9];
    const float* fc1_w   = (const float*)d_in[10];
    const float* fc1_b   = (const float*)d_in[11];
    const float* fc2_w   = (const float*)d_in[12];
    const float* fc2_b   = (const float*)d_in[13];
    float* outp = (float*)d_out;

    __nv_bfloat16 *bh1, *bh2, *bh3, *wt;
    float *bufB;
    cudaGetSymbolAddress((void**)&bh1, g_bh1);
    cudaGetSymbolAddress((void**)&bh2, g_bh2);
    cudaGetSymbolAddress((void**)&bh3, g_bh3);
    cudaGetSymbolAddress((void**)&wt, g_wt);
    cudaGetSymbolAddress((void**)&bufB, g_bufB);

    cudaFuncSetAttribute(attn_mma_kernel, cudaFuncAttributeMaxDynamicSharedMemorySize,
                         ASMEM_ELEMS * 2);
    cudaFuncSetAttribute(lnqkv_kernel,
                         cudaFuncAttributeMaxDynamicSharedMemorySize, NL_SMEM);
    cudaFuncSetAttribute(ffn_kernel,
                         cudaFuncAttributeMaxDynamicSharedMemorySize, FF_SMEM);

    // combined prep (weights + bias/mask table)
    prep_kernel<<<(PREP_TOTAL + 255) / 256, 256>>>(qkv_w, proj_w, fc1_w, fc2_w, rpb);

    // fused LN1 + gather + QKV GEMM -> bh1 bf16 [M,384]
    lnqkv_kernel<<<MROWS / 128, 256, NL_SMEM>>>(
        x, norm1_g, norm1_b, wt + WT_QKV, qkv_b, bh1);

    // attention -> bh2 bf16 (window layout)
    attn_mma_kernel<<<BWIN * 4, 224, ASMEM_ELEMS * 2>>>(bh1, bh2);

    // proj GEMM fused with scatter + residual + LN2 -> bh3 (bf16), bufB (x2)
    proj_fused_kernel<<<MROWS / 128, 256, GEMM_SMEM>>>(
        bh2, wt + WT_PROJ, proj_b, bh3, x, norm2_g, norm2_b, bufB);

    // fused interleaved FFN -> d_out fp32
    ffn_kernel<<<MROWS / 64, 256, FF_SMEM>>>(
        bh3, wt + WT_FC1, wt + WT_FC2, fc1_b, fc2_b, bufB, outp);
}